// round 14
// baseline (speedup 1.0000x reference)
#include <cuda_runtime.h>
#include <math.h>

#define NB 64          // batch
#define SEQ 64         // seq len
#define MD 256         // model dim
#define HF 128         // half
#define WD 300         // word dim
#define MLPD 1024
#define NC 3
#define BKT 16         // K tile
#define NKT (MD / BKT) // 16 k-tiles
#define BM 32          // rows per block (4 warps x 8 rows)
#define XP 36          // Xs row stride in floats (32 + pad; 144B rows, 16B-aligned)

// Scratch (device globals — no runtime allocation allowed)
__device__ float g_states[2][NB * SEQ * MD];     // ping-pong state buffers
__device__ float g_comp[NB * (SEQ - 1) * MD];    // TreeLSTM [h,c] outputs
__device__ float g_lgpart[NB * (SEQ - 1) * 4];   // selection-logit partials (4 j-chunks)

__device__ __forceinline__ float sig_f(float x) { return 1.0f / (1.0f + __expf(-x)); }
__device__ __forceinline__ float tanh_f(float x) { return 1.0f - 2.0f / (__expf(2.0f * x) + 1.0f); }

// Packed f32x2 helpers (sm_100a; ptxas never auto-fuses these)
__device__ __forceinline__ unsigned long long pack2(float lo, float hi) {
    unsigned long long p;
    asm("mov.b64 %0, {%1, %2};" : "=l"(p) : "f"(lo), "f"(hi));
    return p;
}
__device__ __forceinline__ void unpack2(unsigned long long p, float& lo, float& hi) {
    asm("mov.b64 {%0, %1}, %2;" : "=f"(lo), "=f"(hi) : "l"(p));
}
__device__ __forceinline__ void fma2(unsigned long long& d, unsigned long long a, unsigned long long b) {
    asm("fma.rn.f32x2 %0, %1, %2, %0;" : "+l"(d) : "l"(a), "l"(b));
}
__device__ __forceinline__ void cp_async16(void* smem_dst, const void* gmem_src) {
    unsigned sa = (unsigned)__cvta_generic_to_shared(smem_dst);
    asm volatile("cp.async.cg.shared.global [%0], [%1], 16;" :: "r"(sa), "l"(gmem_src));
}
__device__ __forceinline__ void cp_commit() { asm volatile("cp.async.commit_group;"); }
__device__ __forceinline__ void cp_wait0()  { asm volatile("cp.async.wait_group 0;" ::: "memory"); }

// ---------------------------------------------------------------------------
// Encoder: states0[b][t][:] = embed[sent[b][t]] @ W_enc + b_enc
// ---------------------------------------------------------------------------
__global__ void encode_kernel(const int* __restrict__ sent,
                              const float* __restrict__ emb,
                              const float* __restrict__ W,
                              const float* __restrict__ bias) {
    __shared__ float se[16][WD];
    const int tok0 = blockIdx.x * 16;
    const int tid = threadIdx.x;
    for (int i = tid; i < 16 * WD; i += 256) {
        int t = i / WD, k = i - t * WD;
        se[t][k] = emb[(size_t)sent[tok0 + t] * WD + k];
    }
    __syncthreads();
    const int n = tid;
    float acc[16];
    float bv = bias[n];
#pragma unroll
    for (int t = 0; t < 16; t++) acc[t] = bv;
    for (int k = 0; k < WD; k++) {
        float w = W[k * MD + n];
#pragma unroll
        for (int t = 0; t < 16; t++) acc[t] += se[t][k] * w;
    }
    float* out = g_states[0];
#pragma unroll
    for (int t = 0; t < 16; t++) out[(size_t)(tok0 + t) * MD + n] = acc[t];
}

// ---------------------------------------------------------------------------
// Fused GEMM + TreeLSTM cell + logit partial — ROW-PAIR f32x2 packing,
// X operand loaded DIRECTLY as packed ulonglong2 (no pack movs, no dep chain).
// Block: BM=32 rows x 32 gate-cols (jc = blockIdx.y in 0..3) x 5 gates.
// Warp ty owns rows [ty*8, ty*8+8); lane tx owns gate column j = jc*32+tx.
// Per k-step: 20 FFMA2 + 2 LDS.128 (X, broadcast) + 5 LDS.32 (W) + 5 movs.
// ---------------------------------------------------------------------------
__global__ __launch_bounds__(128, 4)
void gates_gemm(const float* __restrict__ Wc, const float* __restrict__ bc,
                const float* __restrict__ Wsel, int P, int in) {
    __shared__ float Xs[2][BKT][XP];
    __shared__ float Ws[2][BKT * 160];     // [k][g*32 + tx], 32-col slice of each gate

    const float* __restrict__ S = g_states[in];
    const int tid = threadIdx.x;
    const int tx = tid & 31, ty = tid >> 5;
    const int jc = blockIdx.y;             // 0..3
    const int j = jc * 32 + tx;            // this lane's gate column
    const int m0 = blockIdx.x * BM;

    // X loader: row mA (0..31), quad kqA (0..3); 128 threads exactly cover tile
    const int mA = tid >> 2;
    const int kqA = tid & 3;
    int roffA;
    {
        int r = m0 + mA;
        int b = r / P;
        roffA = b * (SEQ * MD) + (r - b * P) * MD;
    }

    unsigned long long acc[5][4];
#pragma unroll
    for (int g = 0; g < 5; g++)
#pragma unroll
        for (int rp = 0; rp < 4; rp++) acc[g][rp] = 0ull;

    float4 xr;

    // W prefetch: BKT*160 floats = 640 float4, 5 per thread. chunk=(k*5+g), 8 f4 each.
    auto prefW = [&](int kt, int buf) {
        const float* base = Wc + (size_t)kt * 640 + jc * 32;
#pragma unroll
        for (int it = 0; it < 5; it++) {
            int I = it * 128 + tid;
            int chunk = I >> 3;            // 0..79
            int j4 = I & 7;                // 0..7
            int k = chunk / 5;
            int g = chunk - k * 5;
            cp_async16(&Ws[buf][k * 160 + g * 32 + j4 * 4],
                       base + (size_t)k * 640 + g * 128 + j4 * 4);
        }
    };
    auto ldX = [&](int kt) {
        int kg = kt + kqA * 4;
        int xoff = kg + ((kg >= HF) ? HF : 0);
        xr = *reinterpret_cast<const float4*>(S + roffA + xoff);
    };
    auto stX = [&](int buf) {
        float* xp = &Xs[buf][kqA * 4][mA];
        xp[0 * XP] = xr.x; xp[1 * XP] = xr.y;
        xp[2 * XP] = xr.z; xp[3 * XP] = xr.w;
    };

    // Prologue: tile 0
    prefW(0, 0);
    cp_commit();
    ldX(0);
    stX(0);
    cp_wait0();
    __syncthreads();

    int buf = 0;
    for (int u = 0; u < NKT; u++, buf ^= 1) {
        if (u + 1 < NKT) {
            prefW((u + 1) * BKT, buf ^ 1);
            cp_commit();
            ldX((u + 1) * BKT);
        }
        // W-scalar register double-buffer across k (break LDS->FFMA dependency)
        float w0s, w1s, w2s, w3s, w4s, p0s, p1s, p2s, p3s, p4s;
        {
            const float* wp = &Ws[buf][0] + tx;
            w0s = wp[0]; w1s = wp[32]; w2s = wp[64]; w3s = wp[96]; w4s = wp[128];
        }
#pragma unroll
        for (int k = 0; k < BKT; k++) {
            if (k + 1 < BKT) {
                const float* wp = &Ws[buf][(k + 1) * 160] + tx;
                p0s = wp[0]; p1s = wp[32]; p2s = wp[64]; p3s = wp[96]; p4s = wp[128];
            }
            unsigned long long w0 = pack2(w0s, w0s);
            unsigned long long w1 = pack2(w1s, w1s);
            unsigned long long w2 = pack2(w2s, w2s);
            unsigned long long w3 = pack2(w3s, w3s);
            unsigned long long w4 = pack2(w4s, w4s);
            // Broadcast X: 8 rows = 4 packed row-pairs, loaded directly as 2 x LDS.128
            const ulonglong2* xpp = reinterpret_cast<const ulonglong2*>(&Xs[buf][k][ty * 8]);
            ulonglong2 xA = xpp[0];            // a0 = rows(0,1), a1 = rows(2,3)
            ulonglong2 xB = xpp[1];            // a2 = rows(4,5), a3 = rows(6,7)
            fma2(acc[0][0], xA.x, w0); fma2(acc[1][0], xA.x, w1); fma2(acc[2][0], xA.x, w2);
            fma2(acc[3][0], xA.x, w3); fma2(acc[4][0], xA.x, w4);
            fma2(acc[0][1], xA.y, w0); fma2(acc[1][1], xA.y, w1); fma2(acc[2][1], xA.y, w2);
            fma2(acc[3][1], xA.y, w3); fma2(acc[4][1], xA.y, w4);
            fma2(acc[0][2], xB.x, w0); fma2(acc[1][2], xB.x, w1); fma2(acc[2][2], xB.x, w2);
            fma2(acc[3][2], xB.x, w3); fma2(acc[4][2], xB.x, w4);
            fma2(acc[0][3], xB.y, w0); fma2(acc[1][3], xB.y, w1); fma2(acc[2][3], xB.y, w2);
            fma2(acc[3][3], xB.y, w3); fma2(acc[4][3], xB.y, w4);
            if (k + 1 < BKT) { w0s = p0s; w1s = p1s; w2s = p2s; w3s = p3s; w4s = p4s; }
        }
        if (u + 1 < NKT) stX(buf ^ 1);
        cp_wait0();
        __syncthreads();
    }

    // Epilogue: bias + TreeLSTM cell + comp write + logit partial.
    const float wsh = Wsel[j];
    const float wsc = Wsel[HF + j];
    const float b0 = bc[j];
    const float b1 = bc[128 + j];
    const float b2 = bc[256 + j];
    const float b3 = bc[384 + j];
    const float b4 = bc[512 + j];
#pragma unroll
    for (int rp = 0; rp < 4; rp++) {
        float av[2], iv[2], f1v[2], f2v[2], ov[2];
        unpack2(acc[0][rp], av[0], av[1]);
        unpack2(acc[1][rp], iv[0], iv[1]);
        unpack2(acc[2][rp], f1v[0], f1v[1]);
        unpack2(acc[3][rp], f2v[0], f2v[1]);
        unpack2(acc[4][rp], ov[0], ov[1]);
#pragma unroll
        for (int s = 0; s < 2; s++) {
            int r = m0 + ty * 8 + 2 * rp + s;
            int b = r / P;
            int roff = b * (SEQ * MD) + (r - b * P) * MD;
            float c_l = S[roff + HF + j];
            float c_r = S[roff + MD + HF + j];
            float c = tanh_f(av[s] + b0) * sig_f(iv[s] + b1)
                    + sig_f(f1v[s] + b2) * c_l + sig_f(f2v[s] + b3) * c_r;
            float h = sig_f(ov[s] + b4) * tanh_f(c);
            float* cp = g_comp + (size_t)r * MD;
            cp[j] = h;
            cp[HF + j] = c;
            float part = h * wsh + c * wsc;
#pragma unroll
            for (int o = 16; o > 0; o >>= 1) part += __shfl_xor_sync(0xFFFFFFFFu, part, o);
            if (tx == 0) g_lgpart[r * 4 + jc] = part;
        }
    }
}

// ---------------------------------------------------------------------------
// Per-layer softmax + soft state update. 4 blocks per batch row.
// Softmax done entirely in warp 0 via shfl scan (2 elements/lane, 1 barrier).
// ---------------------------------------------------------------------------
__global__ __launch_bounds__(256)
void update_kernel(int P, int in) {
    __shared__ float prw[64], clw[64], crw[64];
    const int b = blockIdx.x >> 2, q = blockIdx.x & 3;
    const int tid = threadIdx.x;

    if (tid < 32) {
        const int p0 = tid, p1 = tid + 32;
        float l0 = -3.0e38f, l1 = -3.0e38f;
        if (p0 < P) {
            float4 v = *reinterpret_cast<const float4*>(g_lgpart + (((size_t)b * P + p0) << 2));
            l0 = (v.x + v.y) + (v.z + v.w);
        }
        if (p1 < P) {
            float4 v = *reinterpret_cast<const float4*>(g_lgpart + (((size_t)b * P + p1) << 2));
            l1 = (v.x + v.y) + (v.z + v.w);
        }
        float m = fmaxf(l0, l1);
#pragma unroll
        for (int o = 16; o > 0; o >>= 1) m = fmaxf(m, __shfl_xor_sync(0xFFFFFFFFu, m, o));
        float e0 = (p0 < P) ? __expf(l0 - m) : 0.f;
        float e1 = (p1 < P) ? __expf(l1 - m) : 0.f;
        // inclusive scan of the 64-slot sequence [e0(lanes 0..31), e1(lanes 0..31)]
        float s0 = e0;
#pragma unroll
        for (int o = 1; o < 32; o <<= 1) {
            float t = __shfl_up_sync(0xFFFFFFFFu, s0, o);
            if (tid >= o) s0 += t;
        }
        float tot0 = __shfl_sync(0xFFFFFFFFu, s0, 31);
        float s1 = e1;
#pragma unroll
        for (int o = 1; o < 32; o <<= 1) {
            float t = __shfl_up_sync(0xFFFFFFFFu, s1, o);
            if (tid >= o) s1 += t;
        }
        s1 += tot0;
        float tot = __shfl_sync(0xFFFFFFFFu, s1, 31);   // padding e==0 -> equals csn[P-1]
        float inv = 1.f / tot;
        prw[p0] = e0 * inv; crw[p0] = (s0 - e0) * inv; clw[p0] = (tot - s0) * inv;
        prw[p1] = e1 * inv; crw[p1] = (s1 - e1) * inv; clw[p1] = (tot - s1) * inv;
    }
    __syncthreads();

    const float* Sb = g_states[in] + b * SEQ * MD;
    float* Ob = g_states[in ^ 1] + b * SEQ * MD;
    const float* Cb = g_comp + (size_t)b * P * MD;
    for (int p = q; p < P; p += 4) {
        Ob[p * MD + tid] = clw[p] * Sb[p * MD + tid]
                         + crw[p] * Sb[(p + 1) * MD + tid]
                         + prw[p] * Cb[p * MD + tid];
    }
}

// ---------------------------------------------------------------------------
// Final MLP: relu(relu(h@W1+b1)@W2+b2)@W_out + b_out. One block per row.
// ---------------------------------------------------------------------------
__global__ void mlp_kernel(const float* __restrict__ W1, const float* __restrict__ b1,
                           const float* __restrict__ W2, const float* __restrict__ b2,
                           const float* __restrict__ Wo, const float* __restrict__ bo,
                           float* __restrict__ out, int in) {
    const int b = blockIdx.x, tid = threadIdx.x;
    __shared__ float h0[MD];
    __shared__ float h1[MLPD];
    __shared__ float h2[MLPD];
    __shared__ float red[256];
    const float* S = g_states[in] + (size_t)b * SEQ * MD;
    for (int i = tid; i < MD; i += 256) h0[i] = S[i];
    __syncthreads();
#pragma unroll
    for (int ni = 0; ni < MLPD / 256; ni++) {
        int n = tid + ni * 256;
        float acc = b1[n];
        for (int k = 0; k < MD; k++) acc += h0[k] * W1[(size_t)k * MLPD + n];
        h1[n] = fmaxf(acc, 0.f);
    }
    __syncthreads();
#pragma unroll
    for (int ni = 0; ni < MLPD / 256; ni++) {
        int n = tid + ni * 256;
        float acc = b2[n];
        for (int k = 0; k < MLPD; k++) acc += h1[k] * W2[(size_t)k * MLPD + n];
        h2[n] = fmaxf(acc, 0.f);
    }
    __syncthreads();
    for (int c = 0; c < NC; c++) {
        float part = 0.f;
        for (int k = tid; k < MLPD; k += 256) part += h2[k] * Wo[(size_t)k * NC + c];
        red[tid] = part;
        __syncthreads();
        for (int s = 128; s > 0; s >>= 1) {
            if (tid < s) red[tid] += red[tid + s];
            __syncthreads();
        }
        if (tid == 0) out[b * NC + c] = red[0] + bo[c];
        __syncthreads();
    }
}

// ---------------------------------------------------------------------------
extern "C" void kernel_launch(void* const* d_in, const int* in_sizes, int n_in,
                              void* d_out, int out_size) {
    const int*   sent   = (const int*)  d_in[0];
    const float* emb    = (const float*)d_in[1];
    const float* W_enc  = (const float*)d_in[2];
    const float* b_enc  = (const float*)d_in[3];
    const float* W_comp = (const float*)d_in[4];
    const float* b_comp = (const float*)d_in[5];
    const float* W_sel  = (const float*)d_in[6];
    // d_in[7] = b_sel (constant shift, softmax-invariant — not needed)
    const float* W1     = (const float*)d_in[8];
    const float* b1     = (const float*)d_in[9];
    const float* W2     = (const float*)d_in[10];
    const float* b2     = (const float*)d_in[11];
    const float* Wo     = (const float*)d_in[12];
    const float* bo     = (const float*)d_in[13];
    float* out = (float*)d_out;

    encode_kernel<<<NB * SEQ / 16, 256>>>(sent, emb, W_enc, b_enc);

    int cur = 0;
    for (int P = SEQ - 1; P >= 1; --P) {
        dim3 grid(NB * P / BM, 4);       // 64P always divisible by 32
        gates_gemm<<<grid, 128>>>(W_comp, b_comp, W_sel, P, cur);
        update_kernel<<<NB * 4, 256>>>(P, cur);
        cur ^= 1;
    }

    mlp_kernel<<<NB, 256>>>(W1, b1, W2, b2, Wo, bo, out, 1);  // 63 layers -> parity 1
}

// round 15
// speedup vs baseline: 1.0078x; 1.0078x over previous
#include <cuda_runtime.h>
#include <math.h>

#define NB 64          // batch
#define SEQ 64         // seq len
#define MD 256         // model dim
#define HF 128         // half
#define WD 300         // word dim
#define MLPD 1024
#define NC 3
#define BKT 16         // K tile
#define NKT (MD / BKT) // 16 k-tiles
#define BM 32          // rows per block (4 warps x 8 rows)
#define XP 36          // Xs row stride in floats (32 + pad; 144B rows, 16B-aligned)

// Scratch (device globals — no runtime allocation allowed)
__device__ float g_states[2][NB * SEQ * MD];     // ping-pong state buffers
__device__ float g_comp[NB * (SEQ - 1) * MD];    // TreeLSTM [h,c] outputs
__device__ float g_lgpart[NB * (SEQ - 1) * 4];   // selection-logit partials (4 j-chunks)

__device__ __forceinline__ float sig_f(float x) { return 1.0f / (1.0f + __expf(-x)); }
__device__ __forceinline__ float tanh_f(float x) { return 1.0f - 2.0f / (__expf(2.0f * x) + 1.0f); }

// Packed f32x2 helpers (sm_100a; ptxas never auto-fuses these)
__device__ __forceinline__ unsigned long long pack2(float lo, float hi) {
    unsigned long long p;
    asm("mov.b64 %0, {%1, %2};" : "=l"(p) : "f"(lo), "f"(hi));
    return p;
}
__device__ __forceinline__ void unpack2(unsigned long long p, float& lo, float& hi) {
    asm("mov.b64 {%0, %1}, %2;" : "=f"(lo), "=f"(hi) : "l"(p));
}
__device__ __forceinline__ void fma2(unsigned long long& d, unsigned long long a, unsigned long long b) {
    asm("fma.rn.f32x2 %0, %1, %2, %0;" : "+l"(d) : "l"(a), "l"(b));
}
__device__ __forceinline__ void cp_async16(void* smem_dst, const void* gmem_src) {
    unsigned sa = (unsigned)__cvta_generic_to_shared(smem_dst);
    asm volatile("cp.async.cg.shared.global [%0], [%1], 16;" :: "r"(sa), "l"(gmem_src));
}
__device__ __forceinline__ void cp_commit() { asm volatile("cp.async.commit_group;"); }
__device__ __forceinline__ void cp_wait0()  { asm volatile("cp.async.wait_group 0;" ::: "memory"); }

// ---------------------------------------------------------------------------
// Encoder: states0[b][t][:] = embed[sent[b][t]] @ W_enc + b_enc
// ---------------------------------------------------------------------------
__global__ void encode_kernel(const int* __restrict__ sent,
                              const float* __restrict__ emb,
                              const float* __restrict__ W,
                              const float* __restrict__ bias) {
    __shared__ float se[16][WD];
    const int tok0 = blockIdx.x * 16;
    const int tid = threadIdx.x;
    for (int i = tid; i < 16 * WD; i += 256) {
        int t = i / WD, k = i - t * WD;
        se[t][k] = emb[(size_t)sent[tok0 + t] * WD + k];
    }
    __syncthreads();
    const int n = tid;
    float acc[16];
    float bv = bias[n];
#pragma unroll
    for (int t = 0; t < 16; t++) acc[t] = bv;
    for (int k = 0; k < WD; k++) {
        float w = W[k * MD + n];
#pragma unroll
        for (int t = 0; t < 16; t++) acc[t] += se[t][k] * w;
    }
    float* out = g_states[0];
#pragma unroll
    for (int t = 0; t < 16; t++) out[(size_t)(tok0 + t) * MD + n] = acc[t];
}

// ---------------------------------------------------------------------------
// Fused GEMM + TreeLSTM cell + logit partial — ROW-PAIR f32x2 packing with
// BOTH operands software-pipelined across k-steps: X row-pairs (ulonglong2)
// and W scalars are prefetched for k+1 before k's 20 FFMA2s, so no LDS
// latency is exposed inside the inner loop.
// Block: BM=32 rows x 32 gate-cols (jc = blockIdx.y in 0..3) x 5 gates.
// Warp ty owns rows [ty*8, ty*8+8); lane tx owns gate column j = jc*32+tx.
// ---------------------------------------------------------------------------
__global__ __launch_bounds__(128, 4)
void gates_gemm(const float* __restrict__ Wc, const float* __restrict__ bc,
                const float* __restrict__ Wsel, int P, int in) {
    __shared__ float Xs[2][BKT][XP];
    __shared__ float Ws[2][BKT * 160];     // [k][g*32 + tx], 32-col slice of each gate

    const float* __restrict__ S = g_states[in];
    const int tid = threadIdx.x;
    const int tx = tid & 31, ty = tid >> 5;
    const int jc = blockIdx.y;             // 0..3
    const int j = jc * 32 + tx;            // this lane's gate column
    const int m0 = blockIdx.x * BM;

    // X loader: row mA (0..31), quad kqA (0..3); 128 threads exactly cover tile
    const int mA = tid >> 2;
    const int kqA = tid & 3;
    int roffA;
    {
        int r = m0 + mA;
        int b = r / P;
        roffA = b * (SEQ * MD) + (r - b * P) * MD;
    }

    unsigned long long acc[5][4];
#pragma unroll
    for (int g = 0; g < 5; g++)
#pragma unroll
        for (int rp = 0; rp < 4; rp++) acc[g][rp] = 0ull;

    float4 xr;

    // W prefetch: BKT*160 floats = 640 float4, 5 per thread. chunk=(k*5+g), 8 f4 each.
    auto prefW = [&](int kt, int buf) {
        const float* base = Wc + (size_t)kt * 640 + jc * 32;
#pragma unroll
        for (int it = 0; it < 5; it++) {
            int I = it * 128 + tid;
            int chunk = I >> 3;            // 0..79
            int j4 = I & 7;                // 0..7
            int k = chunk / 5;
            int g = chunk - k * 5;
            cp_async16(&Ws[buf][k * 160 + g * 32 + j4 * 4],
                       base + (size_t)k * 640 + g * 128 + j4 * 4);
        }
    };
    auto ldX = [&](int kt) {
        int kg = kt + kqA * 4;
        int xoff = kg + ((kg >= HF) ? HF : 0);
        xr = *reinterpret_cast<const float4*>(S + roffA + xoff);
    };
    auto stX = [&](int buf) {
        float* xp = &Xs[buf][kqA * 4][mA];
        xp[0 * XP] = xr.x; xp[1 * XP] = xr.y;
        xp[2 * XP] = xr.z; xp[3 * XP] = xr.w;
    };

    // Prologue: tile 0
    prefW(0, 0);
    cp_commit();
    ldX(0);
    stX(0);
    cp_wait0();
    __syncthreads();

    int buf = 0;
    for (int u = 0; u < NKT; u++, buf ^= 1) {
        if (u + 1 < NKT) {
            prefW((u + 1) * BKT, buf ^ 1);
            cp_commit();
            ldX((u + 1) * BKT);
        }
        // Both-operand register double-buffer across k: no exposed LDS latency.
        float w0s, w1s, w2s, w3s, w4s, p0s, p1s, p2s, p3s, p4s;
        ulonglong2 xA, xB, nxA, nxB;
        {
            const float* wp = &Ws[buf][0] + tx;
            w0s = wp[0]; w1s = wp[32]; w2s = wp[64]; w3s = wp[96]; w4s = wp[128];
            const ulonglong2* xpp = reinterpret_cast<const ulonglong2*>(&Xs[buf][0][ty * 8]);
            xA = xpp[0];
            xB = xpp[1];
        }
#pragma unroll
        for (int k = 0; k < BKT; k++) {
            if (k + 1 < BKT) {
                const float* wp = &Ws[buf][(k + 1) * 160] + tx;
                p0s = wp[0]; p1s = wp[32]; p2s = wp[64]; p3s = wp[96]; p4s = wp[128];
                const ulonglong2* xpp =
                    reinterpret_cast<const ulonglong2*>(&Xs[buf][k + 1][ty * 8]);
                nxA = xpp[0];
                nxB = xpp[1];
            }
            unsigned long long w0 = pack2(w0s, w0s);
            unsigned long long w1 = pack2(w1s, w1s);
            unsigned long long w2 = pack2(w2s, w2s);
            unsigned long long w3 = pack2(w3s, w3s);
            unsigned long long w4 = pack2(w4s, w4s);
            fma2(acc[0][0], xA.x, w0); fma2(acc[1][0], xA.x, w1); fma2(acc[2][0], xA.x, w2);
            fma2(acc[3][0], xA.x, w3); fma2(acc[4][0], xA.x, w4);
            fma2(acc[0][1], xA.y, w0); fma2(acc[1][1], xA.y, w1); fma2(acc[2][1], xA.y, w2);
            fma2(acc[3][1], xA.y, w3); fma2(acc[4][1], xA.y, w4);
            fma2(acc[0][2], xB.x, w0); fma2(acc[1][2], xB.x, w1); fma2(acc[2][2], xB.x, w2);
            fma2(acc[3][2], xB.x, w3); fma2(acc[4][2], xB.x, w4);
            fma2(acc[0][3], xB.y, w0); fma2(acc[1][3], xB.y, w1); fma2(acc[2][3], xB.y, w2);
            fma2(acc[3][3], xB.y, w3); fma2(acc[4][3], xB.y, w4);
            if (k + 1 < BKT) {
                w0s = p0s; w1s = p1s; w2s = p2s; w3s = p3s; w4s = p4s;
                xA = nxA; xB = nxB;
            }
        }
        if (u + 1 < NKT) stX(buf ^ 1);
        cp_wait0();
        __syncthreads();
    }

    // Epilogue: bias + TreeLSTM cell + comp write + logit partial.
    const float wsh = Wsel[j];
    const float wsc = Wsel[HF + j];
    const float b0 = bc[j];
    const float b1 = bc[128 + j];
    const float b2 = bc[256 + j];
    const float b3 = bc[384 + j];
    const float b4 = bc[512 + j];
#pragma unroll
    for (int rp = 0; rp < 4; rp++) {
        float av[2], iv[2], f1v[2], f2v[2], ov[2];
        unpack2(acc[0][rp], av[0], av[1]);
        unpack2(acc[1][rp], iv[0], iv[1]);
        unpack2(acc[2][rp], f1v[0], f1v[1]);
        unpack2(acc[3][rp], f2v[0], f2v[1]);
        unpack2(acc[4][rp], ov[0], ov[1]);
#pragma unroll
        for (int s = 0; s < 2; s++) {
            int r = m0 + ty * 8 + 2 * rp + s;
            int b = r / P;
            int roff = b * (SEQ * MD) + (r - b * P) * MD;
            float c_l = S[roff + HF + j];
            float c_r = S[roff + MD + HF + j];
            float c = tanh_f(av[s] + b0) * sig_f(iv[s] + b1)
                    + sig_f(f1v[s] + b2) * c_l + sig_f(f2v[s] + b3) * c_r;
            float h = sig_f(ov[s] + b4) * tanh_f(c);
            float* cp = g_comp + (size_t)r * MD;
            cp[j] = h;
            cp[HF + j] = c;
            float part = h * wsh + c * wsc;
#pragma unroll
            for (int o = 16; o > 0; o >>= 1) part += __shfl_xor_sync(0xFFFFFFFFu, part, o);
            if (tx == 0) g_lgpart[r * 4 + jc] = part;
        }
    }
}

// ---------------------------------------------------------------------------
// Per-layer softmax + soft state update. 4 blocks per batch row.
// Softmax done entirely in warp 0 via shfl scan (2 elements/lane, 1 barrier).
// ---------------------------------------------------------------------------
__global__ __launch_bounds__(256)
void update_kernel(int P, int in) {
    __shared__ float prw[64], clw[64], crw[64];
    const int b = blockIdx.x >> 2, q = blockIdx.x & 3;
    const int tid = threadIdx.x;

    if (tid < 32) {
        const int p0 = tid, p1 = tid + 32;
        float l0 = -3.0e38f, l1 = -3.0e38f;
        if (p0 < P) {
            float4 v = *reinterpret_cast<const float4*>(g_lgpart + (((size_t)b * P + p0) << 2));
            l0 = (v.x + v.y) + (v.z + v.w);
        }
        if (p1 < P) {
            float4 v = *reinterpret_cast<const float4*>(g_lgpart + (((size_t)b * P + p1) << 2));
            l1 = (v.x + v.y) + (v.z + v.w);
        }
        float m = fmaxf(l0, l1);
#pragma unroll
        for (int o = 16; o > 0; o >>= 1) m = fmaxf(m, __shfl_xor_sync(0xFFFFFFFFu, m, o));
        float e0 = (p0 < P) ? __expf(l0 - m) : 0.f;
        float e1 = (p1 < P) ? __expf(l1 - m) : 0.f;
        // inclusive scan of the 64-slot sequence [e0(lanes 0..31), e1(lanes 0..31)]
        float s0 = e0;
#pragma unroll
        for (int o = 1; o < 32; o <<= 1) {
            float t = __shfl_up_sync(0xFFFFFFFFu, s0, o);
            if (tid >= o) s0 += t;
        }
        float tot0 = __shfl_sync(0xFFFFFFFFu, s0, 31);
        float s1 = e1;
#pragma unroll
        for (int o = 1; o < 32; o <<= 1) {
            float t = __shfl_up_sync(0xFFFFFFFFu, s1, o);
            if (tid >= o) s1 += t;
        }
        s1 += tot0;
        float tot = __shfl_sync(0xFFFFFFFFu, s1, 31);   // padding e==0 -> equals csn[P-1]
        float inv = 1.f / tot;
        prw[p0] = e0 * inv; crw[p0] = (s0 - e0) * inv; clw[p0] = (tot - s0) * inv;
        prw[p1] = e1 * inv; crw[p1] = (s1 - e1) * inv; clw[p1] = (tot - s1) * inv;
    }
    __syncthreads();

    const float* Sb = g_states[in] + b * SEQ * MD;
    float* Ob = g_states[in ^ 1] + b * SEQ * MD;
    const float* Cb = g_comp + (size_t)b * P * MD;
    for (int p = q; p < P; p += 4) {
        Ob[p * MD + tid] = clw[p] * Sb[p * MD + tid]
                         + crw[p] * Sb[(p + 1) * MD + tid]
                         + prw[p] * Cb[p * MD + tid];
    }
}

// ---------------------------------------------------------------------------
// Final MLP: relu(relu(h@W1+b1)@W2+b2)@W_out + b_out. One block per row.
// ---------------------------------------------------------------------------
__global__ void mlp_kernel(const float* __restrict__ W1, const float* __restrict__ b1,
                           const float* __restrict__ W2, const float* __restrict__ b2,
                           const float* __restrict__ Wo, const float* __restrict__ bo,
                           float* __restrict__ out, int in) {
    const int b = blockIdx.x, tid = threadIdx.x;
    __shared__ float h0[MD];
    __shared__ float h1[MLPD];
    __shared__ float h2[MLPD];
    __shared__ float red[256];
    const float* S = g_states[in] + (size_t)b * SEQ * MD;
    for (int i = tid; i < MD; i += 256) h0[i] = S[i];
    __syncthreads();
#pragma unroll
    for (int ni = 0; ni < MLPD / 256; ni++) {
        int n = tid + ni * 256;
        float acc = b1[n];
        for (int k = 0; k < MD; k++) acc += h0[k] * W1[(size_t)k * MLPD + n];
        h1[n] = fmaxf(acc, 0.f);
    }
    __syncthreads();
#pragma unroll
    for (int ni = 0; ni < MLPD / 256; ni++) {
        int n = tid + ni * 256;
        float acc = b2[n];
        for (int k = 0; k < MLPD; k++) acc += h1[k] * W2[(size_t)k * MLPD + n];
        h2[n] = fmaxf(acc, 0.f);
    }
    __syncthreads();
    for (int c = 0; c < NC; c++) {
        float part = 0.f;
        for (int k = tid; k < MLPD; k += 256) part += h2[k] * Wo[(size_t)k * NC + c];
        red[tid] = part;
        __syncthreads();
        for (int s = 128; s > 0; s >>= 1) {
            if (tid < s) red[tid] += red[tid + s];
            __syncthreads();
        }
        if (tid == 0) out[b * NC + c] = red[0] + bo[c];
        __syncthreads();
    }
}

// ---------------------------------------------------------------------------
extern "C" void kernel_launch(void* const* d_in, const int* in_sizes, int n_in,
                              void* d_out, int out_size) {
    const int*   sent   = (const int*)  d_in[0];
    const float* emb    = (const float*)d_in[1];
    const float* W_enc  = (const float*)d_in[2];
    const float* b_enc  = (const float*)d_in[3];
    const float* W_comp = (const float*)d_in[4];
    const float* b_comp = (const float*)d_in[5];
    const float* W_sel  = (const float*)d_in[6];
    // d_in[7] = b_sel (constant shift, softmax-invariant — not needed)
    const float* W1     = (const float*)d_in[8];
    const float* b1     = (const float*)d_in[9];
    const float* W2     = (const float*)d_in[10];
    const float* b2     = (const float*)d_in[11];
    const float* Wo     = (const float*)d_in[12];
    const float* bo     = (const float*)d_in[13];
    float* out = (float*)d_out;

    encode_kernel<<<NB * SEQ / 16, 256>>>(sent, emb, W_enc, b_enc);

    int cur = 0;
    for (int P = SEQ - 1; P >= 1; --P) {
        dim3 grid(NB * P / BM, 4);       // 64P always divisible by 32
        gates_gemm<<<grid, 128>>>(W_comp, b_comp, W_sel, P, cur);
        update_kernel<<<NB * 4, 256>>>(P, cur);
        cur ^= 1;
    }

    mlp_kernel<<<NB, 256>>>(W1, b1, W2, b2, Wo, bo, out, 1);  // 63 layers -> parity 1
}

// round 16
// speedup vs baseline: 1.0321x; 1.0241x over previous
#include <cuda_runtime.h>
#include <math.h>

#define NB 64          // batch
#define SEQ 64         // seq len
#define MD 256         // model dim
#define HF 128         // half
#define WD 300         // word dim
#define MLPD 1024
#define NC 3
#define BKT 16         // K tile
#define NKT (MD / BKT) // 16 k-tiles
#define BM 16          // rows per block (4 warps x 4 rows) -> 992 blocks @P=62
#define XP 20          // Xs row stride in floats (16 + pad; 80B rows, 16B-aligned)

// Scratch (device globals — no runtime allocation allowed)
__device__ float g_states[2][NB * SEQ * MD];     // ping-pong state buffers
__device__ float g_comp[NB * (SEQ - 1) * MD];    // TreeLSTM [h,c] outputs
__device__ float g_lgpart[NB * (SEQ - 1) * 4];   // selection-logit partials (4 j-chunks)

__device__ __forceinline__ float sig_f(float x) { return 1.0f / (1.0f + __expf(-x)); }
__device__ __forceinline__ float tanh_f(float x) { return 1.0f - 2.0f / (__expf(2.0f * x) + 1.0f); }

// Packed f32x2 helpers (sm_100a; ptxas never auto-fuses these)
__device__ __forceinline__ unsigned long long pack2(float lo, float hi) {
    unsigned long long p;
    asm("mov.b64 %0, {%1, %2};" : "=l"(p) : "f"(lo), "f"(hi));
    return p;
}
__device__ __forceinline__ void unpack2(unsigned long long p, float& lo, float& hi) {
    asm("mov.b64 {%0, %1}, %2;" : "=f"(lo), "=f"(hi) : "l"(p));
}
__device__ __forceinline__ void fma2(unsigned long long& d, unsigned long long a, unsigned long long b) {
    asm("fma.rn.f32x2 %0, %1, %2, %0;" : "+l"(d) : "l"(a), "l"(b));
}
__device__ __forceinline__ void cp_async16(void* smem_dst, const void* gmem_src) {
    unsigned sa = (unsigned)__cvta_generic_to_shared(smem_dst);
    asm volatile("cp.async.cg.shared.global [%0], [%1], 16;" :: "r"(sa), "l"(gmem_src));
}
__device__ __forceinline__ void cp_commit() { asm volatile("cp.async.commit_group;"); }
__device__ __forceinline__ void cp_wait0()  { asm volatile("cp.async.wait_group 0;" ::: "memory"); }

// ---------------------------------------------------------------------------
// Encoder: states0[b][t][:] = embed[sent[b][t]] @ W_enc + b_enc
// ---------------------------------------------------------------------------
__global__ void encode_kernel(const int* __restrict__ sent,
                              const float* __restrict__ emb,
                              const float* __restrict__ W,
                              const float* __restrict__ bias) {
    __shared__ float se[16][WD];
    const int tok0 = blockIdx.x * 16;
    const int tid = threadIdx.x;
    for (int i = tid; i < 16 * WD; i += 256) {
        int t = i / WD, k = i - t * WD;
        se[t][k] = emb[(size_t)sent[tok0 + t] * WD + k];
    }
    __syncthreads();
    const int n = tid;
    float acc[16];
    float bv = bias[n];
#pragma unroll
    for (int t = 0; t < 16; t++) acc[t] = bv;
    for (int k = 0; k < WD; k++) {
        float w = W[k * MD + n];
#pragma unroll
        for (int t = 0; t < 16; t++) acc[t] += se[t][k] * w;
    }
    float* out = g_states[0];
#pragma unroll
    for (int t = 0; t < 16; t++) out[(size_t)(tok0 + t) * MD + n] = acc[t];
}

// ---------------------------------------------------------------------------
// Fused GEMM + TreeLSTM cell + logit partial — high-occupancy variant.
// Block: BM=16 rows x 32 gate-cols (jc = blockIdx.y in 0..3) x 5 gates.
// Warp ty owns rows [ty*4, ty*4+4) (2 packed row-pairs); lane tx owns gate
// column j = jc*32+tx. Grid = 4P x 4 -> 3968 warps (6.7/SMSP): latency hidden
// by occupancy, not manual pipelining. Per k-step: 10 FFMA2 + 1 LDS.128 (X,
// broadcast) + 5 LDS.32 (W) + 5 pack movs — issue and fma-pipe balanced.
// ---------------------------------------------------------------------------
__global__ __launch_bounds__(128, 6)
void gates_gemm(const float* __restrict__ Wc, const float* __restrict__ bc,
                const float* __restrict__ Wsel, int P, int in) {
    __shared__ float Xs[2][BKT][XP];
    __shared__ float Ws[2][BKT * 160];     // [k][g*32 + tx], 32-col slice of each gate

    const float* __restrict__ S = g_states[in];
    const int tid = threadIdx.x;
    const int tx = tid & 31, ty = tid >> 5;
    const int jc = blockIdx.y;             // 0..3
    const int j = jc * 32 + tx;            // this lane's gate column
    const int m0 = blockIdx.x * BM;

    // X loader: row mA (0..15), quad kqA (0..3); threads 0..63
    const int mA = tid >> 2;
    const int kqA = tid & 3;
    const bool hasA = (mA < BM);
    int roffA = 0;
    if (hasA) {
        int r = m0 + mA;
        int b = r / P;
        roffA = b * (SEQ * MD) + (r - b * P) * MD;
    }

    unsigned long long acc[5][2];
#pragma unroll
    for (int g = 0; g < 5; g++)
#pragma unroll
        for (int rp = 0; rp < 2; rp++) acc[g][rp] = 0ull;

    float4 xr;

    // W prefetch: BKT*160 floats = 640 float4, 5 per thread. chunk=(k*5+g), 8 f4 each.
    auto prefW = [&](int kt, int buf) {
        const float* base = Wc + (size_t)kt * 640 + jc * 32;
#pragma unroll
        for (int it = 0; it < 5; it++) {
            int I = it * 128 + tid;
            int chunk = I >> 3;            // 0..79
            int j4 = I & 7;                // 0..7
            int k = chunk / 5;
            int g = chunk - k * 5;
            cp_async16(&Ws[buf][k * 160 + g * 32 + j4 * 4],
                       base + (size_t)k * 640 + g * 128 + j4 * 4);
        }
    };
    auto ldX = [&](int kt) {
        if (hasA) {
            int kg = kt + kqA * 4;
            int xoff = kg + ((kg >= HF) ? HF : 0);
            xr = *reinterpret_cast<const float4*>(S + roffA + xoff);
        }
    };
    auto stX = [&](int buf) {
        if (hasA) {
            float* xp = &Xs[buf][kqA * 4][mA];
            xp[0 * XP] = xr.x; xp[1 * XP] = xr.y;
            xp[2 * XP] = xr.z; xp[3 * XP] = xr.w;
        }
    };

    // Prologue: tile 0
    prefW(0, 0);
    cp_commit();
    ldX(0);
    stX(0);
    cp_wait0();
    __syncthreads();

    int buf = 0;
    for (int u = 0; u < NKT; u++, buf ^= 1) {
        if (u + 1 < NKT) {
            prefW((u + 1) * BKT, buf ^ 1);
            cp_commit();
            ldX((u + 1) * BKT);
        }
#pragma unroll
        for (int k = 0; k < BKT; k++) {
            const float* wp = &Ws[buf][k * 160] + tx;
            float w0s = wp[0], w1s = wp[32], w2s = wp[64], w3s = wp[96], w4s = wp[128];
            unsigned long long w0 = pack2(w0s, w0s);
            unsigned long long w1 = pack2(w1s, w1s);
            unsigned long long w2 = pack2(w2s, w2s);
            unsigned long long w3 = pack2(w3s, w3s);
            unsigned long long w4 = pack2(w4s, w4s);
            // Broadcast X: 4 rows = 2 packed row-pairs, one LDS.128
            ulonglong2 xA = *reinterpret_cast<const ulonglong2*>(&Xs[buf][k][ty * 4]);
            fma2(acc[0][0], xA.x, w0); fma2(acc[1][0], xA.x, w1); fma2(acc[2][0], xA.x, w2);
            fma2(acc[3][0], xA.x, w3); fma2(acc[4][0], xA.x, w4);
            fma2(acc[0][1], xA.y, w0); fma2(acc[1][1], xA.y, w1); fma2(acc[2][1], xA.y, w2);
            fma2(acc[3][1], xA.y, w3); fma2(acc[4][1], xA.y, w4);
        }
        if (u + 1 < NKT) stX(buf ^ 1);
        cp_wait0();
        __syncthreads();
    }

    // Epilogue: bias + TreeLSTM cell + comp write + logit partial.
    const float wsh = Wsel[j];
    const float wsc = Wsel[HF + j];
    const float b0 = bc[j];
    const float b1 = bc[128 + j];
    const float b2 = bc[256 + j];
    const float b3 = bc[384 + j];
    const float b4 = bc[512 + j];
#pragma unroll
    for (int rp = 0; rp < 2; rp++) {
        float av[2], iv[2], f1v[2], f2v[2], ov[2];
        unpack2(acc[0][rp], av[0], av[1]);
        unpack2(acc[1][rp], iv[0], iv[1]);
        unpack2(acc[2][rp], f1v[0], f1v[1]);
        unpack2(acc[3][rp], f2v[0], f2v[1]);
        unpack2(acc[4][rp], ov[0], ov[1]);
#pragma unroll
        for (int s = 0; s < 2; s++) {
            int r = m0 + ty * 4 + 2 * rp + s;
            int b = r / P;
            int roff = b * (SEQ * MD) + (r - b * P) * MD;
            float c_l = S[roff + HF + j];
            float c_r = S[roff + MD + HF + j];
            float c = tanh_f(av[s] + b0) * sig_f(iv[s] + b1)
                    + sig_f(f1v[s] + b2) * c_l + sig_f(f2v[s] + b3) * c_r;
            float h = sig_f(ov[s] + b4) * tanh_f(c);
            float* cp = g_comp + (size_t)r * MD;
            cp[j] = h;
            cp[HF + j] = c;
            float part = h * wsh + c * wsc;
#pragma unroll
            for (int o = 16; o > 0; o >>= 1) part += __shfl_xor_sync(0xFFFFFFFFu, part, o);
            if (tx == 0) g_lgpart[r * 4 + jc] = part;
        }
    }
}

// ---------------------------------------------------------------------------
// Per-layer softmax + soft state update. 4 blocks per batch row.
// Softmax done entirely in warp 0 via shfl scan (2 elements/lane, 1 barrier).
// ---------------------------------------------------------------------------
__global__ __launch_bounds__(256)
void update_kernel(int P, int in) {
    __shared__ float prw[64], clw[64], crw[64];
    const int b = blockIdx.x >> 2, q = blockIdx.x & 3;
    const int tid = threadIdx.x;

    if (tid < 32) {
        const int p0 = tid, p1 = tid + 32;
        float l0 = -3.0e38f, l1 = -3.0e38f;
        if (p0 < P) {
            float4 v = *reinterpret_cast<const float4*>(g_lgpart + (((size_t)b * P + p0) << 2));
            l0 = (v.x + v.y) + (v.z + v.w);
        }
        if (p1 < P) {
            float4 v = *reinterpret_cast<const float4*>(g_lgpart + (((size_t)b * P + p1) << 2));
            l1 = (v.x + v.y) + (v.z + v.w);
        }
        float m = fmaxf(l0, l1);
#pragma unroll
        for (int o = 16; o > 0; o >>= 1) m = fmaxf(m, __shfl_xor_sync(0xFFFFFFFFu, m, o));
        float e0 = (p0 < P) ? __expf(l0 - m) : 0.f;
        float e1 = (p1 < P) ? __expf(l1 - m) : 0.f;
        // inclusive scan of the 64-slot sequence [e0(lanes 0..31), e1(lanes 0..31)]
        float s0 = e0;
#pragma unroll
        for (int o = 1; o < 32; o <<= 1) {
            float t = __shfl_up_sync(0xFFFFFFFFu, s0, o);
            if (tid >= o) s0 += t;
        }
        float tot0 = __shfl_sync(0xFFFFFFFFu, s0, 31);
        float s1 = e1;
#pragma unroll
        for (int o = 1; o < 32; o <<= 1) {
            float t = __shfl_up_sync(0xFFFFFFFFu, s1, o);
            if (tid >= o) s1 += t;
        }
        s1 += tot0;
        float tot = __shfl_sync(0xFFFFFFFFu, s1, 31);   // padding e==0 -> equals csn[P-1]
        float inv = 1.f / tot;
        prw[p0] = e0 * inv; crw[p0] = (s0 - e0) * inv; clw[p0] = (tot - s0) * inv;
        prw[p1] = e1 * inv; crw[p1] = (s1 - e1) * inv; clw[p1] = (tot - s1) * inv;
    }
    __syncthreads();

    const float* Sb = g_states[in] + b * SEQ * MD;
    float* Ob = g_states[in ^ 1] + b * SEQ * MD;
    const float* Cb = g_comp + (size_t)b * P * MD;
    for (int p = q; p < P; p += 4) {
        Ob[p * MD + tid] = clw[p] * Sb[p * MD + tid]
                         + crw[p] * Sb[(p + 1) * MD + tid]
                         + prw[p] * Cb[p * MD + tid];
    }
}

// ---------------------------------------------------------------------------
// Final MLP: relu(relu(h@W1+b1)@W2+b2)@W_out + b_out. One block per row.
// ---------------------------------------------------------------------------
__global__ void mlp_kernel(const float* __restrict__ W1, const float* __restrict__ b1,
                           const float* __restrict__ W2, const float* __restrict__ b2,
                           const float* __restrict__ Wo, const float* __restrict__ bo,
                           float* __restrict__ out, int in) {
    const int b = blockIdx.x, tid = threadIdx.x;
    __shared__ float h0[MD];
    __shared__ float h1[MLPD];
    __shared__ float h2[MLPD];
    __shared__ float red[256];
    const float* S = g_states[in] + (size_t)b * SEQ * MD;
    for (int i = tid; i < MD; i += 256) h0[i] = S[i];
    __syncthreads();
#pragma unroll
    for (int ni = 0; ni < MLPD / 256; ni++) {
        int n = tid + ni * 256;
        float acc = b1[n];
        for (int k = 0; k < MD; k++) acc += h0[k] * W1[(size_t)k * MLPD + n];
        h1[n] = fmaxf(acc, 0.f);
    }
    __syncthreads();
#pragma unroll
    for (int ni = 0; ni < MLPD / 256; ni++) {
        int n = tid + ni * 256;
        float acc = b2[n];
        for (int k = 0; k < MLPD; k++) acc += h1[k] * W2[(size_t)k * MLPD + n];
        h2[n] = fmaxf(acc, 0.f);
    }
    __syncthreads();
    for (int c = 0; c < NC; c++) {
        float part = 0.f;
        for (int k = tid; k < MLPD; k += 256) part += h2[k] * Wo[(size_t)k * NC + c];
        red[tid] = part;
        __syncthreads();
        for (int s = 128; s > 0; s >>= 1) {
            if (tid < s) red[tid] += red[tid + s];
            __syncthreads();
        }
        if (tid == 0) out[b * NC + c] = red[0] + bo[c];
        __syncthreads();
    }
}

// ---------------------------------------------------------------------------
extern "C" void kernel_launch(void* const* d_in, const int* in_sizes, int n_in,
                              void* d_out, int out_size) {
    const int*   sent   = (const int*)  d_in[0];
    const float* emb    = (const float*)d_in[1];
    const float* W_enc  = (const float*)d_in[2];
    const float* b_enc  = (const float*)d_in[3];
    const float* W_comp = (const float*)d_in[4];
    const float* b_comp = (const float*)d_in[5];
    const float* W_sel  = (const float*)d_in[6];
    // d_in[7] = b_sel (constant shift, softmax-invariant — not needed)
    const float* W1     = (const float*)d_in[8];
    const float* b1     = (const float*)d_in[9];
    const float* W2     = (const float*)d_in[10];
    const float* b2     = (const float*)d_in[11];
    const float* Wo     = (const float*)d_in[12];
    const float* bo     = (const float*)d_in[13];
    float* out = (float*)d_out;

    encode_kernel<<<NB * SEQ / 16, 256>>>(sent, emb, W_enc, b_enc);

    int cur = 0;
    for (int P = SEQ - 1; P >= 1; --P) {
        dim3 grid(NB * P / BM, 4);       // 64P always divisible by 16
        gates_gemm<<<grid, 128>>>(W_comp, b_comp, W_sel, P, cur);
        update_kernel<<<NB * 4, 256>>>(P, cur);
        cur ^= 1;
    }

    mlp_kernel<<<NB, 256>>>(W1, b1, W2, b2, Wo, bo, out, 1);  // 63 layers -> parity 1
}